// round 15
// baseline (speedup 1.0000x reference)
#include <cuda_runtime.h>

#define NB_NODES 4096
#define NB_EMAX  2048
#define NB_L     8
#define NB_HID   128
#define NB_TH    256
#define NB_SMAX  256    // max start edges per graph (E/G = 16 expected)

// ---------------------------------------------------------------------------
// Fused chain entry: s_chain[p] = next(16b, 0xFFFF=null) | src_p << 16.
// Walking bucket `node` enumerates all edges p with dst_p == node; dst_p is
// implicit, so each step is a single LDS.
//
// walk<K>(node=src_cur, forb=dst_cur, start): iterates successors p (depth K)
// of the depth-(K-1) edge cur; rule dst_p == src_cur && src_p != dst_cur.
// p == start closes a non-backtracking walk of length K -> cnt[K-1]
// (= diag(B^K)). Fully inlined; all per-depth state in registers.
// ---------------------------------------------------------------------------
template<int K>
__device__ __forceinline__ void walk(const int* __restrict__ sh,
                                     const int* __restrict__ sc,
                                     int node, int forb, int start, int* cnt) {
    if constexpr (K <= NB_L) {
        int p = sh[node];
        while (p >= 0) {
            const int e   = sc[p];
            const int spn = e >> 16;        // src_p
            const int nxt = e & 0xFFFF;
            if (spn != forb) {              // not backtracking
                if (p == start) cnt[K - 1]++;
                walk<K + 1>(sh, sc, spn, node, start, cnt);
            }
            p = (nxt == 0xFFFF) ? -1 : nxt;
        }
    }
}

// ---------------------------------------------------------------------------
// One block per graph; fully independent blocks. 256 threads: lower per-block
// launch/ramp + barrier cost (walk work is proven tiny, so fewer warps is ok).
// ---------------------------------------------------------------------------
__global__ __launch_bounds__(NB_TH, 1)
void k_graph(const int* __restrict__ ei, const int* __restrict__ eg,
             const float* __restrict__ W1, const float* __restrict__ b1,
             const float* __restrict__ W2, const float* __restrict__ b2,
             float* __restrict__ out, int E) {
    __shared__ int   s_head[NB_NODES];     // 16 KB (int: shared atomicExch target)
    __shared__ int   s_chain[NB_EMAX];     //  8 KB  next(16b) | src(16b)
    __shared__ int2  s_starts[NB_SMAX];    //  2 KB  {edge id, src<<16|dst}
    __shared__ int   s_ns;
    __shared__ int   s_sigv[NB_L];         // integer closed-walk counts
    __shared__ float s_part[4];

    const int g    = blockIdx.x;
    const int tid  = threadIdx.x;
    const int lane = tid & 31;
    const int warp = tid >> 5;

    // ---- 0: PREFETCH global data into registers at kernel entry ----
    // Two int4-triples per thread (quads tid and tid+256); all 6 LDG.128
    // issue back-to-back so their latency overlaps init + barrier.
    const int4* ei4 = (const int4*)ei;
    const int4* eg4 = (const int4*)eg;
    const int nq = E >> 2;                 // E = 2048 -> 512 quads
    const int ta = tid, tb = tid + NB_TH;
    int4 sa, da, ga, sb, db, gb;
    const bool ha = (ta < nq), hb = (tb < nq);
    if (ha) { sa = ei4[ta]; da = ei4[nq + ta]; ga = eg4[ta]; }
    if (hb) { sb = ei4[tb]; db = ei4[nq + tb]; gb = eg4[tb]; }
    float w[NB_L], b1v = 0.0f, w2v = 0.0f;
    if (tid < NB_HID) {
#pragma unroll
        for (int l = 0; l < NB_L; l++) w[l] = __ldg(&W1[l * NB_HID + tid]);
        b1v = __ldg(&b1[tid]);
        w2v = __ldg(&W2[tid]);
    }

    // ---- 1: init head (vectorized) / counters (overlaps prefetch latency) --
    {
        int4* h4 = (int4*)s_head;
        const int4 mv = make_int4(-1, -1, -1, -1);
#pragma unroll
        for (int v = tid; v < NB_NODES / 4; v += NB_TH) h4[v] = mv;
    }
    if (tid < NB_L) s_sigv[tid] = 0;
    if (tid == 0)  s_ns = 0;
    __syncthreads();

    // ---- 2: fused build + start collection (both prefetched quads) --------
    if (ha) {
        const int j = ta << 2;
        const int o0 = atomicExch(&s_head[da.x], j + 0);
        const int o1 = atomicExch(&s_head[da.y], j + 1);
        const int o2 = atomicExch(&s_head[da.z], j + 2);
        const int o3 = atomicExch(&s_head[da.w], j + 3);
        s_chain[j + 0] = (o0 & 0xFFFF) | (sa.x << 16);
        s_chain[j + 1] = (o1 & 0xFFFF) | (sa.y << 16);
        s_chain[j + 2] = (o2 & 0xFFFF) | (sa.z << 16);
        s_chain[j + 3] = (o3 & 0xFFFF) | (sa.w << 16);
        if (ga.x == g) { int p = atomicAdd(&s_ns, 1); if (p < NB_SMAX) s_starts[p] = make_int2(j + 0, (sa.x << 16) | da.x); }
        if (ga.y == g) { int p = atomicAdd(&s_ns, 1); if (p < NB_SMAX) s_starts[p] = make_int2(j + 1, (sa.y << 16) | da.y); }
        if (ga.z == g) { int p = atomicAdd(&s_ns, 1); if (p < NB_SMAX) s_starts[p] = make_int2(j + 2, (sa.z << 16) | da.z); }
        if (ga.w == g) { int p = atomicAdd(&s_ns, 1); if (p < NB_SMAX) s_starts[p] = make_int2(j + 3, (sa.w << 16) | da.w); }
    }
    if (hb) {
        const int j = tb << 2;
        const int o0 = atomicExch(&s_head[db.x], j + 0);
        const int o1 = atomicExch(&s_head[db.y], j + 1);
        const int o2 = atomicExch(&s_head[db.z], j + 2);
        const int o3 = atomicExch(&s_head[db.w], j + 3);
        s_chain[j + 0] = (o0 & 0xFFFF) | (sb.x << 16);
        s_chain[j + 1] = (o1 & 0xFFFF) | (sb.y << 16);
        s_chain[j + 2] = (o2 & 0xFFFF) | (sb.z << 16);
        s_chain[j + 3] = (o3 & 0xFFFF) | (sb.w << 16);
        if (gb.x == g) { int p = atomicAdd(&s_ns, 1); if (p < NB_SMAX) s_starts[p] = make_int2(j + 0, (sb.x << 16) | db.x); }
        if (gb.y == g) { int p = atomicAdd(&s_ns, 1); if (p < NB_SMAX) s_starts[p] = make_int2(j + 1, (sb.y << 16) | db.y); }
        if (gb.z == g) { int p = atomicAdd(&s_ns, 1); if (p < NB_SMAX) s_starts[p] = make_int2(j + 2, (sb.z << 16) | db.z); }
        if (gb.w == g) { int p = atomicAdd(&s_ns, 1); if (p < NB_SMAX) s_starts[p] = make_int2(j + 3, (sb.w << 16) | db.w); }
    }
    // generic fallback for unexpected shapes (no-op when nq <= 2*NB_TH)
    for (int t = tid + 2 * NB_TH; t < nq; t += NB_TH) {
        const int4 s4 = ei4[t], d4 = ei4[nq + t], g4 = eg4[t];
        const int j = t << 2;
        const int dd[4] = { d4.x, d4.y, d4.z, d4.w };
        const int ss[4] = { s4.x, s4.y, s4.z, s4.w };
        const int gg[4] = { g4.x, g4.y, g4.z, g4.w };
#pragma unroll
        for (int c = 0; c < 4; c++) {
            const int o = atomicExch(&s_head[dd[c]], j + c);
            s_chain[j + c] = (o & 0xFFFF) | (ss[c] << 16);
            if (gg[c] == g) { int p = atomicAdd(&s_ns, 1); if (p < NB_SMAX) s_starts[p] = make_int2(j + c, (ss[c] << 16) | dd[c]); }
        }
    }
    __syncthreads();

    // ---- 3: warp-per-start DFS, lane-strided depth-1 children -------------
    // length-1 closure is structurally impossible (self-loop && non-self-loop).
    int cnt[NB_L];
#pragma unroll
    for (int k = 0; k < NB_L; k++) cnt[k] = 0;

    const int ns = min(s_ns, NB_SMAX);
    for (int si = warp; si < ns; si += NB_TH >> 5) {
        const int2 st  = s_starts[si];
        const int id   = st.x;
        const int isrc = st.y >> 16;
        const int idst = st.y & 0xFFFF;
        int idx = 0;
        int p = s_head[isrc];
        while (p >= 0) {
            const int e   = s_chain[p];
            const int spn = e >> 16;                    // src_p
            const int nxt = e & 0xFFFF;
            if (spn != idst) {                          // not backtracking
                if ((idx++ & 31) == lane)               // stride over lanes
                    walk<2>(s_head, s_chain, spn, isrc, id, cnt);
            }
            p = (nxt == 0xFFFF) ? -1 : nxt;
        }
    }
#pragma unroll
    for (int k = 1; k < NB_L; k++) {
        int v = cnt[k];
#pragma unroll
        for (int o = 16; o; o >>= 1) v += __shfl_xor_sync(0xffffffffu, v, o);
        if (lane == 0 && v) atomicAdd(&s_sigv[k], v);
    }
    __syncthreads();

    // ---- 4: MLP for this graph --------------------------------------------
    float v = 0.0f;
    if (tid < NB_HID) {
        float h = b1v;
#pragma unroll
        for (int l = 0; l < NB_L; l++)
            h = fmaf((float)s_sigv[l], w[l], h);
        v = fmaxf(h, 0.0f) * w2v;
    }
#pragma unroll
    for (int o = 16; o; o >>= 1) v += __shfl_xor_sync(0xffffffffu, v, o);
    if (tid < NB_HID && lane == 0) s_part[warp] = v;
    __syncthreads();
    if (tid == 0) {
        float tot = __ldg(&b2[0]);
#pragma unroll
        for (int ww = 0; ww < NB_HID / 32; ww++) tot += s_part[ww];
        out[g] = tot;
    }
}

extern "C" void kernel_launch(void* const* d_in, const int* in_sizes, int n_in,
                              void* d_out, int out_size) {
    const int*   ei = (const int*)  d_in[0];   // edge_index [2, E]
    const int*   eg = (const int*)  d_in[1];   // edge_graph [E]
    const float* W1 = (const float*)d_in[2];   // [L, HID]
    const float* b1 = (const float*)d_in[3];   // [HID]
    const float* W2 = (const float*)d_in[4];   // [HID, 1]
    const float* b2 = (const float*)d_in[5];   // [1]
    float* out = (float*)d_out;                // [G, 1]

    const int E = in_sizes[0] / 2;
    const int G = out_size;

    k_graph<<<G, NB_TH>>>(ei, eg, W1, b1, W2, b2, out, E);
}

// round 16
// speedup vs baseline: 1.0694x; 1.0694x over previous
#include <cuda_runtime.h>

#define NB_NODES 4096
#define NB_EMAX  2048
#define NB_L     8
#define NB_HID   128
#define NB_TH    1024
#define NB_SMAX  256    // max start edges per graph (E/G = 16 expected)

// ---------------------------------------------------------------------------
// Fused chain entry: s_chain[p] = next(16b, 0xFFFF=null) | src_p << 16.
// Walking bucket `node` enumerates all edges p with dst_p == node; dst_p is
// implicit, so each step is a single LDS.
//
// walk<K>(node=src_cur, forb=dst_cur, start): iterates successors p (depth K)
// of the depth-(K-1) edge cur; rule dst_p == src_cur && src_p != dst_cur.
// p == start closes a non-backtracking walk of length K -> cnt[K-1]
// (= diag(B^K)). Fully inlined; all per-depth state in registers.
// ---------------------------------------------------------------------------
template<int K>
__device__ __forceinline__ void walk(const int* __restrict__ sh,
                                     const int* __restrict__ sc,
                                     int node, int forb, int start, int* cnt) {
    if constexpr (K <= NB_L) {
        int p = sh[node];
        while (p >= 0) {
            const int e   = sc[p];
            const int spn = e >> 16;        // src_p
            const int nxt = e & 0xFFFF;
            if (spn != forb) {              // not backtracking
                if (p == start) cnt[K - 1]++;
                walk<K + 1>(sh, sc, spn, node, start, cnt);
            }
            p = (nxt == 0xFFFF) ? -1 : nxt;
        }
    }
}

// ---------------------------------------------------------------------------
// One block per graph; fully independent blocks. 1024 threads: each thread
// owns 2 edges -> build/init per-thread work halves vs the 512 version
// (R15 showed per-thread serial work is on the critical path).
// ---------------------------------------------------------------------------
__global__ __launch_bounds__(NB_TH, 1)
void k_graph(const int* __restrict__ ei, const int* __restrict__ eg,
             const float* __restrict__ W1, const float* __restrict__ b1,
             const float* __restrict__ W2, const float* __restrict__ b2,
             float* __restrict__ out, int E) {
    __shared__ int   s_head[NB_NODES];     // 16 KB (int: shared atomicExch target)
    __shared__ int   s_chain[NB_EMAX];     //  8 KB  next(16b) | src(16b)
    __shared__ int2  s_starts[NB_SMAX];    //  2 KB  {edge id, src<<16|dst}
    __shared__ int   s_ns;
    __shared__ int   s_sigv[NB_L];         // integer closed-walk counts
    __shared__ float s_part[4];

    const int g    = blockIdx.x;
    const int tid  = threadIdx.x;
    const int lane = tid & 31;
    const int warp = tid >> 5;

    // ---- 0: PREFETCH global data into registers at kernel entry ----
    // One edge-pair per thread: 3 independent LDG.64 issue back-to-back so
    // their latency overlaps the head init + barrier.
    const int2* ei2 = (const int2*)ei;
    const int2* eg2 = (const int2*)eg;
    const int nh = E >> 1;                 // E = 2048 -> 1024 pairs (== NB_TH)
    int2 sp, dp, gp;
    const int t0 = tid;
    if (t0 < nh) {
        sp = ei2[t0];
        dp = ei2[nh + t0];
        gp = eg2[t0];
    }
    float w[NB_L], b1v = 0.0f, w2v = 0.0f;
    if (tid < NB_HID) {
#pragma unroll
        for (int l = 0; l < NB_L; l++) w[l] = __ldg(&W1[l * NB_HID + tid]);
        b1v = __ldg(&b1[tid]);
        w2v = __ldg(&W2[tid]);
    }

    // ---- 1: init head (vectorized) / counters (overlaps prefetch latency) --
    {
        int4* h4 = (int4*)s_head;
        const int4 mv = make_int4(-1, -1, -1, -1);
#pragma unroll
        for (int v = tid; v < NB_NODES / 4; v += NB_TH) h4[v] = mv;
    }
    if (tid < NB_L) s_sigv[tid] = 0;
    if (tid == 0)  s_ns = 0;
    __syncthreads();

    // ---- 2: fused build + start collection (prefetched pair) --------------
    for (int t = t0; t < nh; t += NB_TH) {
        if (t != t0) { sp = ei2[t]; dp = ei2[nh + t]; gp = eg2[t]; }
        const int j = t << 1;
        const int o0 = atomicExch(&s_head[dp.x], j + 0);
        const int o1 = atomicExch(&s_head[dp.y], j + 1);
        s_chain[j + 0] = (o0 & 0xFFFF) | (sp.x << 16);
        s_chain[j + 1] = (o1 & 0xFFFF) | (sp.y << 16);
        if (gp.x == g) { int p = atomicAdd(&s_ns, 1); if (p < NB_SMAX) s_starts[p] = make_int2(j + 0, (sp.x << 16) | dp.x); }
        if (gp.y == g) { int p = atomicAdd(&s_ns, 1); if (p < NB_SMAX) s_starts[p] = make_int2(j + 1, (sp.y << 16) | dp.y); }
    }
    __syncthreads();

    // ---- 3: warp-per-start DFS, lane-strided depth-1 children -------------
    // length-1 closure is structurally impossible (self-loop && non-self-loop).
    int cnt[NB_L];
#pragma unroll
    for (int k = 0; k < NB_L; k++) cnt[k] = 0;

    const int ns = min(s_ns, NB_SMAX);
    for (int si = warp; si < ns; si += NB_TH >> 5) {
        const int2 st  = s_starts[si];
        const int id   = st.x;
        const int isrc = st.y >> 16;
        const int idst = st.y & 0xFFFF;
        int idx = 0;
        int p = s_head[isrc];
        while (p >= 0) {
            const int e   = s_chain[p];
            const int spn = e >> 16;                    // src_p
            const int nxt = e & 0xFFFF;
            if (spn != idst) {                          // not backtracking
                if ((idx++ & 31) == lane)               // stride over lanes
                    walk<2>(s_head, s_chain, spn, isrc, id, cnt);
            }
            p = (nxt == 0xFFFF) ? -1 : nxt;
        }
    }
#pragma unroll
    for (int k = 1; k < NB_L; k++) {
        int v = cnt[k];
#pragma unroll
        for (int o = 16; o; o >>= 1) v += __shfl_xor_sync(0xffffffffu, v, o);
        if (lane == 0 && v) atomicAdd(&s_sigv[k], v);
    }
    __syncthreads();

    // ---- 4: MLP for this graph --------------------------------------------
    float v = 0.0f;
    if (tid < NB_HID) {
        float h = b1v;
#pragma unroll
        for (int l = 0; l < NB_L; l++)
            h = fmaf((float)s_sigv[l], w[l], h);
        v = fmaxf(h, 0.0f) * w2v;
    }
#pragma unroll
    for (int o = 16; o; o >>= 1) v += __shfl_xor_sync(0xffffffffu, v, o);
    if (tid < NB_HID && lane == 0) s_part[warp] = v;
    __syncthreads();
    if (tid == 0) {
        float tot = __ldg(&b2[0]);
#pragma unroll
        for (int ww = 0; ww < NB_HID / 32; ww++) tot += s_part[ww];
        out[g] = tot;
    }
}

extern "C" void kernel_launch(void* const* d_in, const int* in_sizes, int n_in,
                              void* d_out, int out_size) {
    const int*   ei = (const int*)  d_in[0];   // edge_index [2, E]
    const int*   eg = (const int*)  d_in[1];   // edge_graph [E]
    const float* W1 = (const float*)d_in[2];   // [L, HID]
    const float* b1 = (const float*)d_in[3];   // [HID]
    const float* W2 = (const float*)d_in[4];   // [HID, 1]
    const float* b2 = (const float*)d_in[5];   // [1]
    float* out = (float*)d_out;                // [G, 1]

    const int E = in_sizes[0] / 2;
    const int G = out_size;

    k_graph<<<G, NB_TH>>>(ei, eg, W1, b1, W2, b2, out, E);
}